// round 5
// baseline (speedup 1.0000x reference)
#include <cuda_runtime.h>
#include <cstdint>

#define Dd 1024
#define Bb 16
#define Tt 1024
#define NBLK 128
#define GRPS 4
#define CPG 32      // CTAs (producers/dim-slices) per sync group
#define DC 32       // dims per CTA
#define MAXR 0.999f
#define EPSF 1e-8f

// ---------------- device scratch (no allocation allowed) ----------------
__device__ float g_WhEff[Dd * Dd];                 // 4 MB
__device__ float g_pre[(size_t)Tt * Bb * Dd];      // 64 MB: x @ Wx^T + bias
__device__ float g_sigma;
// per-group 32 producer flags, each group's flags packed in one 128B line
__device__ __align__(128) unsigned g_flags[GRPS * CPG];

// ---------------- f32x2 helpers (sm_103a packed fp32) ----------------
__device__ __forceinline__ float2 up2(unsigned long long v) {
    float2 r;
    asm("mov.b64 {%0, %1}, %2;" : "=f"(r.x), "=f"(r.y) : "l"(v));
    return r;
}
__device__ __forceinline__ void fma2(unsigned long long& d, unsigned long long a,
                                     unsigned long long b) {
    asm("fma.rn.f32x2 %0, %1, %2, %0;" : "+l"(d) : "l"(a), "l"(b));
}
__device__ __forceinline__ unsigned long long add2(unsigned long long a,
                                                   unsigned long long b) {
    unsigned long long r;
    asm("add.rn.f32x2 %0, %1, %2;" : "=l"(r) : "l"(a), "l"(b));
    return r;
}
__device__ __forceinline__ unsigned long long pk2(float lo, float hi) {
    unsigned long long r;
    asm("mov.b64 %0, {%1, %2};" : "=l"(r) : "f"(lo), "f"(hi));
    return r;
}

// ---------------- per-launch init (device globals persist across replays) ---
__global__ void init_kernel() {
    if (threadIdx.x < GRPS * CPG) g_flags[threadIdx.x] = 0u;
}

// ---------------- block-wide sum (1024 threads) ----------------
__device__ __forceinline__ float blk_sum(float v, float* red) {
    int lane = threadIdx.x & 31, warp = threadIdx.x >> 5;
#pragma unroll
    for (int off = 16; off > 0; off >>= 1) v += __shfl_xor_sync(0xffffffffu, v, off);
    if (lane == 0) red[warp] = v;
    __syncthreads();
    if (warp == 0) {
        float x = red[lane];
#pragma unroll
        for (int off = 16; off > 0; off >>= 1) x += __shfl_xor_sync(0xffffffffu, x, off);
        if (lane == 0) red[0] = x;
    }
    __syncthreads();
    float r = red[0];
    __syncthreads();
    return r;
}

// ---------------- 3-step power iteration -> g_sigma ----------------
__global__ void __launch_bounds__(1024) power_iter_kernel(
        const float* __restrict__ Wh, const float* __restrict__ u0) {
    __shared__ float su[Dd];
    __shared__ float sv[Dd];
    __shared__ float red[32];
    const int tid = threadIdx.x;
    su[tid] = u0[tid];
    __syncthreads();

    float normsq_last = 0.f, nu_last = 0.f;
    for (int it = 0; it < 3; it++) {
        float acc = 0.f;
        for (int i = 0; i < Dd; i++) acc += Wh[(size_t)i * Dd + tid] * su[i];
        float nv = sqrtf(blk_sum(acc * acc, red)) + EPSF;
        sv[tid] = acc / nv;
        __syncthreads();
        float acc2 = 0.f;
        const float* row = Wh + (size_t)tid * Dd;
        for (int j = 0; j < Dd; j++) acc2 += row[j] * sv[j];
        float nsq = blk_sum(acc2 * acc2, red);
        float nu = sqrtf(nsq);
        su[tid] = acc2 / (nu + EPSF);
        __syncthreads();
        if (it == 2) { normsq_last = nsq; nu_last = nu; }
    }
    if (tid == 0) g_sigma = fabsf(normsq_last / (nu_last + EPSF));
}

// ---------------- W_h_eff = W_h * radii[i] / (sigma + eps) ----------------
__global__ void __launch_bounds__(256) scale_wh_kernel(
        const float* __restrict__ Wh, const float* __restrict__ log_radii) {
    const int i = blockIdx.x;
    const float r = (1.f / (1.f + expf(-log_radii[i]))) * MAXR;
    const float scale = r / (g_sigma + EPSF);
    const float4* src = (const float4*)(Wh + (size_t)i * Dd);
    float4* dst = (float4*)(g_WhEff + (size_t)i * Dd);
    int j = threadIdx.x;
    float4 v = src[j];
    v.x *= scale; v.y *= scale; v.z *= scale; v.w *= scale;
    dst[j] = v;
}

// ---------------- SGEMM with packed f32x2 FMA ----------------
__global__ void __launch_bounds__(256) gemm_kernel(
        const float* __restrict__ A, const float* __restrict__ W,
        const float* __restrict__ bias) {
    __shared__ float As[16][132];
    __shared__ float Bs[16][132];
    const int tid = threadIdx.x;
    const int tx = tid & 15, ty = tid >> 4;
    const int m0 = blockIdx.y * 128, n0 = blockIdx.x * 128;
    const int lrow = tid >> 2, lcol = (tid & 3) << 2;

    const float* Aptr = A + (size_t)(m0 + lrow) * Dd + lcol;
    const float* Wptr = W + (size_t)(n0 + lrow) * Dd + lcol;

    float4 a0 = *(const float4*)(Aptr);
    float4 a1 = *(const float4*)(Aptr + (size_t)64 * Dd);
    float4 b0 = *(const float4*)(Wptr);
    float4 b1 = *(const float4*)(Wptr + (size_t)64 * Dd);

    unsigned long long acc2[8][4];
#pragma unroll
    for (int i = 0; i < 8; i++)
#pragma unroll
        for (int j = 0; j < 4; j++) acc2[i][j] = 0ULL;

    for (int k0 = 0; k0 < Dd; k0 += 16) {
        __syncthreads();
        As[lcol + 0][lrow] = a0.x; As[lcol + 1][lrow] = a0.y;
        As[lcol + 2][lrow] = a0.z; As[lcol + 3][lrow] = a0.w;
        As[lcol + 0][lrow + 64] = a1.x; As[lcol + 1][lrow + 64] = a1.y;
        As[lcol + 2][lrow + 64] = a1.z; As[lcol + 3][lrow + 64] = a1.w;
        Bs[lcol + 0][lrow] = b0.x; Bs[lcol + 1][lrow] = b0.y;
        Bs[lcol + 2][lrow] = b0.z; Bs[lcol + 3][lrow] = b0.w;
        Bs[lcol + 0][lrow + 64] = b1.x; Bs[lcol + 1][lrow + 64] = b1.y;
        Bs[lcol + 2][lrow + 64] = b1.z; Bs[lcol + 3][lrow + 64] = b1.w;
        __syncthreads();

        if (k0 + 16 < Dd) {
            a0 = *(const float4*)(Aptr + k0 + 16);
            a1 = *(const float4*)(Aptr + (size_t)64 * Dd + k0 + 16);
            b0 = *(const float4*)(Wptr + k0 + 16);
            b1 = *(const float4*)(Wptr + (size_t)64 * Dd + k0 + 16);
        }

#pragma unroll
        for (int k = 0; k < 16; k++) {
            float ar[8];
            *(float4*)(ar) = *(const float4*)&As[k][ty * 8];
            *(float4*)(ar + 4) = *(const float4*)&As[k][ty * 8 + 4];
            unsigned long long brp[4];
            const unsigned long long* b64 = (const unsigned long long*)&Bs[k][tx * 8];
            brp[0] = b64[0]; brp[1] = b64[1]; brp[2] = b64[2]; brp[3] = b64[3];
#pragma unroll
            for (int i = 0; i < 8; i++) {
                unsigned long long ad = pk2(ar[i], ar[i]);
#pragma unroll
                for (int j = 0; j < 4; j++) fma2(acc2[i][j], ad, brp[j]);
            }
        }
    }

    float bj[8];
#pragma unroll
    for (int j = 0; j < 8; j++) bj[j] = bias[n0 + tx * 8 + j];
#pragma unroll
    for (int i = 0; i < 8; i++) {
        float* Crow = g_pre + (size_t)(m0 + ty * 8 + i) * Dd + n0 + tx * 8;
        float c[8];
#pragma unroll
        for (int j = 0; j < 4; j++) {
            float2 f = up2(acc2[i][j]);
            c[2 * j] = f.x + bj[2 * j];
            c[2 * j + 1] = f.y + bj[2 * j + 1];
        }
        *(float4*)(Crow) = make_float4(c[0], c[1], c[2], c[3]);
        *(float4*)(Crow + 4) = make_float4(c[4], c[5], c[6], c[7]);
    }
}

// fast tanh via __expf (rel err ~1e-6, amplified ~2.5x by recurrence; << 1e-3)
__device__ __forceinline__ float ftanh(float x) {
    float e = __expf(2.f * x);
    return 1.f - 2.f / (e + 1.f);
}

// ---------------- persistent recurrence: dataflow wavefront ----------------
// 128 CTAs = 4 groups x 32. Group g owns batches [4g,4g+4). CTA = 32 dims x
// 4 batches, W slice 128KB persistent in SMEM. No group barrier: producer CTA
// j publishes flag[j]=t+1 after writing its h[t+1] slice (hall slabs are
// write-once -> no WAR hazard, flags are monotone). Warp 8 = poller: turns
// the 32 flags into a monotone SMEM avail counter. 8 compute warps consume
// h[t] in 32-k chunks as slices arrive (spin on SMEM, not L2).
// Warp = 4 dims x 4 batches; lane (b,g): b=lane>>3, g=lane&7 owns one 16B
// h granule per chunk; W via LDS.128 with 4x broadcast dedup.
__global__ void __launch_bounds__(288, 1) recurrent_kernel(
        const float* __restrict__ z, const float* __restrict__ h0,
        float* __restrict__ outs, float* __restrict__ hall) {
    extern __shared__ float smem[];
    float* sW = smem;                                  // [DC][Dd] = 128 KB
    unsigned* s_avail = (unsigned*)(smem + DC * Dd);   // monotone chunk counter

    const int tid = threadIdx.x, bid = blockIdx.x;
    const int grp = bid >> 5;               // sync/batch group
    const int cidx = bid & 31;              // producer index within group
    const int dbase = cidx * DC;
    const int bbase = grp * 4;
    unsigned* flags = &g_flags[grp * CPG];  // this group's 32 flags (one line)
    unsigned* myflag = &g_flags[grp * CPG + cidx];

    // preload my W_h_eff rows (persist across all steps)
    {
        const float4* wsrc = (const float4*)(g_WhEff + (size_t)dbase * Dd);
        for (int i = tid; i < DC * Dd / 4; i += 288) ((float4*)sW)[i] = wsrc[i];
    }
    if (tid == 0) *s_avail = 0u;
    // h_all[0] stripe (pure output; consumers read the h0 input directly)
    if (tid < 128) {
        int b = bbase + (tid >> 5), d = dbase + (tid & 31);
        hall[b * Dd + d] = h0[b * Dd + d];
    }
    __syncthreads();

    const int w = tid >> 5, lane = tid & 31;

    if (w == 8) {
        // ---- poller warp: lane j tracks producer j ----
        unsigned last_pub = 0u;
        for (int t = 0; t < Tt; t++) {
            int p = 0;
            const unsigned baset = (unsigned)t * 32u;
            while (p < 32) {
                unsigned f;
                asm volatile("ld.acquire.gpu.global.u32 %0, [%1];"
                             : "=r"(f) : "l"(flags + lane) : "memory");
                unsigned bal = __ballot_sync(0xffffffffu, f >= (unsigned)t);
                int np = (bal == 0xffffffffu) ? 32 : (__ffs(~bal) - 1);
                if (np > p) {
                    p = np;
                    unsigned pub = baset + (unsigned)p;
                    if (lane == 0 && pub > last_pub) {
                        last_pub = pub;
                        asm volatile("st.release.cta.u32 [%0], %1;"
                                     :: "l"(s_avail), "r"(pub) : "memory");
                    }
                }
            }
            __syncthreads();   // join per-step end barrier
        }
        return;
    }

    // ---- compute warps ----
    const int b = lane >> 3, g = lane & 7;
    const int myb = bbase + b;
    const bool epi = (g < 4);
    const int ed = dbase + w * 4 + g;      // valid when epi
    const ulonglong2* w128 = (const ulonglong2*)sW;

    unsigned avail_seen = 0u;
    for (int t = 0; t < Tt; t++) {
        const size_t off_e = (size_t)t * Bb * Dd + (size_t)myb * Dd + ed;
        float pre_v = 0.f, z_v = 0.f;
        if (epi) {                      // DRAM prefetch, overlaps everything
            pre_v = __ldcg(g_pre + off_e);
            z_v = __ldcg(z + off_e);
        }

        const float* hb = ((t == 0) ? h0 : (hall + (size_t)t * Bb * Dd))
                          + (size_t)myb * Dd;
        unsigned long long acc[4] = {0ULL, 0ULL, 0ULL, 0ULL};
        const unsigned baset = (unsigned)t * 32u;

#pragma unroll 1
        for (int jj = 0; jj < 32; jj += 4) {
            const unsigned need = baset + (unsigned)jj + 4u;
            if (avail_seen < need) {
                do {
                    asm volatile("ld.acquire.cta.u32 %0, [%1];"
                                 : "=r"(avail_seen) : "l"(s_avail) : "memory");
                } while (avail_seen < need);
            }
#pragma unroll
            for (int j0 = 0; j0 < 4; j0++) {
                const int j = jj + j0;
                const ulonglong2 hv =
                    __ldcg((const ulonglong2*)(hb + j * 32 + g * 4));
#pragma unroll
                for (int d = 0; d < 4; d++) {
                    const ulonglong2 wv = w128[(w * 4 + d) * 256 + j * 8 + g];
                    fma2(acc[d], wv.x, hv.x);
                    fma2(acc[d], wv.y, hv.y);
                }
            }
        }

        // reduce over the 8-lane g-group (batch fixed).
        // round A: plain xor-4 add; rounds B,C: fold -> lane g<4 owns dim g.
#pragma unroll
        for (int d = 0; d < 4; d++)
            acc[d] = add2(acc[d], __shfl_xor_sync(0xffffffffu, acc[d], 4));
#pragma unroll
        for (int j = 0; j < 2; j++) {
            unsigned long long send = (g & 2) ? acc[j] : acc[j + 2];
            unsigned long long recv = __shfl_xor_sync(0xffffffffu, send, 2);
            acc[j] = add2((g & 2) ? acc[j + 2] : acc[j], recv);
        }
        {
            unsigned long long send = (g & 1) ? acc[0] : acc[1];
            unsigned long long recv = __shfl_xor_sync(0xffffffffu, send, 1);
            acc[0] = add2((g & 1) ? acc[1] : acc[0], recv);
        }
        const float2 f2 = up2(acc[0]);
        const float val = f2.x + f2.y;

        if (epi) {
            float hn = ftanh(val + pre_v);
            hall[off_e + Bb * Dd] = hn;            // h_all[t+1]
            float sg = z_v / (1.f + __expf(-z_v));
            outs[off_e] = hn * sg;
        }
        __syncthreads();                 // all 9 warps: slice fully stored
        if (tid == 0) {
            __threadfence();
            asm volatile("st.release.gpu.global.u32 [%0], %1;"
                         :: "l"(myflag), "r"((unsigned)(t + 1)) : "memory");
        }
    }
}

// ---------------- launch ----------------
extern "C" void kernel_launch(void* const* d_in, const int* in_sizes, int n_in,
                              void* d_out, int out_size) {
    const float* x   = (const float*)d_in[0];  // [T,B,D]
    const float* z   = (const float*)d_in[1];  // [T,B,D]
    const float* h0  = (const float*)d_in[2];  // [B,D]
    const float* Wx  = (const float*)d_in[3];  // [D,D]
    const float* Wh  = (const float*)d_in[4];  // [D,D]
    const float* lr  = (const float*)d_in[5];  // [D]
    const float* bia = (const float*)d_in[6];  // [D]
    const float* u0  = (const float*)d_in[7];  // [D]

    float* outs = (float*)d_out;                         // [T,B,D]
    float* hall = (float*)d_out + (size_t)Tt * Bb * Dd;  // [T+1,B,D]

    const size_t rec_smem = (size_t)DC * Dd * sizeof(float) + 128;  // ~128.1 KB
    cudaFuncSetAttribute(recurrent_kernel,
                         cudaFuncAttributeMaxDynamicSharedMemorySize,
                         (int)rec_smem);

    init_kernel<<<1, 128>>>();
    power_iter_kernel<<<1, 1024>>>(Wh, u0);
    scale_wh_kernel<<<Dd, 256>>>(Wh, lr);
    {
        dim3 grid(Dd / 128, (Tt * Bb) / 128);  // (8, 128)
        gemm_kernel<<<grid, 256>>>(x, Wx, bia);
    }
    recurrent_kernel<<<NBLK, 288, rec_smem>>>(z, h0, outs, hall);
}

// round 10
// speedup vs baseline: 1.3551x; 1.3551x over previous
#include <cuda_runtime.h>
#include <cstdint>

#define Dd 1024
#define Bb 16
#define Tt 1024
#define NBLK 128
#define GRPS 4
#define CPG 32      // CTAs (dim-slices) per sync group
#define DC 32       // dims per CTA
#define MAXR 0.999f
#define EPSF 1e-8f

// ---------------- device scratch (no allocation allowed) ----------------
__device__ float g_WhEff[Dd * Dd];                 // 4 MB
__device__ float g_pre[(size_t)Tt * Bb * Dd];      // 64 MB: x @ Wx^T + bias
__device__ float g_sigma;
// one 128B line of 32 flags per group; producer j owns word j (no atomics)
__device__ __align__(128) unsigned g_flags[GRPS * CPG];

// ---------------- f32x2 helpers (sm_103a packed fp32) ----------------
__device__ __forceinline__ float2 up2(unsigned long long v) {
    float2 r;
    asm("mov.b64 {%0, %1}, %2;" : "=f"(r.x), "=f"(r.y) : "l"(v));
    return r;
}
__device__ __forceinline__ void fma2(unsigned long long& d, unsigned long long a,
                                     unsigned long long b) {
    asm("fma.rn.f32x2 %0, %1, %2, %0;" : "+l"(d) : "l"(a), "l"(b));
}
__device__ __forceinline__ unsigned long long add2(unsigned long long a,
                                                   unsigned long long b) {
    unsigned long long r;
    asm("add.rn.f32x2 %0, %1, %2;" : "=l"(r) : "l"(a), "l"(b));
    return r;
}
__device__ __forceinline__ unsigned long long pk2(float lo, float hi) {
    unsigned long long r;
    asm("mov.b64 %0, {%1, %2};" : "=l"(r) : "f"(lo), "f"(hi));
    return r;
}

// ---------------- per-launch init (device globals persist across replays) ---
__global__ void init_kernel() {
    if (threadIdx.x < GRPS * CPG) g_flags[threadIdx.x] = 0u;
}

// ---------------- block-wide sum (1024 threads) ----------------
__device__ __forceinline__ float blk_sum(float v, float* red) {
    int lane = threadIdx.x & 31, warp = threadIdx.x >> 5;
#pragma unroll
    for (int off = 16; off > 0; off >>= 1) v += __shfl_xor_sync(0xffffffffu, v, off);
    if (lane == 0) red[warp] = v;
    __syncthreads();
    if (warp == 0) {
        float x = red[lane];
#pragma unroll
        for (int off = 16; off > 0; off >>= 1) x += __shfl_xor_sync(0xffffffffu, x, off);
        if (lane == 0) red[0] = x;
    }
    __syncthreads();
    float r = red[0];
    __syncthreads();
    return r;
}

// ---------------- 3-step power iteration -> g_sigma ----------------
__global__ void __launch_bounds__(1024) power_iter_kernel(
        const float* __restrict__ Wh, const float* __restrict__ u0) {
    __shared__ float su[Dd];
    __shared__ float sv[Dd];
    __shared__ float red[32];
    const int tid = threadIdx.x;
    su[tid] = u0[tid];
    __syncthreads();

    float normsq_last = 0.f, nu_last = 0.f;
    for (int it = 0; it < 3; it++) {
        float acc = 0.f;
        for (int i = 0; i < Dd; i++) acc += Wh[(size_t)i * Dd + tid] * su[i];
        float nv = sqrtf(blk_sum(acc * acc, red)) + EPSF;
        sv[tid] = acc / nv;
        __syncthreads();
        float acc2 = 0.f;
        const float* row = Wh + (size_t)tid * Dd;
        for (int j = 0; j < Dd; j++) acc2 += row[j] * sv[j];
        float nsq = blk_sum(acc2 * acc2, red);
        float nu = sqrtf(nsq);
        su[tid] = acc2 / (nu + EPSF);
        __syncthreads();
        if (it == 2) { normsq_last = nsq; nu_last = nu; }
    }
    if (tid == 0) g_sigma = fabsf(normsq_last / (nu_last + EPSF));
}

// ---------------- W_h_eff = W_h * radii[i] / (sigma + eps) ----------------
__global__ void __launch_bounds__(256) scale_wh_kernel(
        const float* __restrict__ Wh, const float* __restrict__ log_radii) {
    const int i = blockIdx.x;
    const float r = (1.f / (1.f + expf(-log_radii[i]))) * MAXR;
    const float scale = r / (g_sigma + EPSF);
    const float4* src = (const float4*)(Wh + (size_t)i * Dd);
    float4* dst = (float4*)(g_WhEff + (size_t)i * Dd);
    int j = threadIdx.x;
    float4 v = src[j];
    v.x *= scale; v.y *= scale; v.z *= scale; v.w *= scale;
    dst[j] = v;
}

// ---------------- SGEMM with packed f32x2 FMA ----------------
__global__ void __launch_bounds__(256) gemm_kernel(
        const float* __restrict__ A, const float* __restrict__ W,
        const float* __restrict__ bias) {
    __shared__ float As[16][132];
    __shared__ float Bs[16][132];
    const int tid = threadIdx.x;
    const int tx = tid & 15, ty = tid >> 4;
    const int m0 = blockIdx.y * 128, n0 = blockIdx.x * 128;
    const int lrow = tid >> 2, lcol = (tid & 3) << 2;

    const float* Aptr = A + (size_t)(m0 + lrow) * Dd + lcol;
    const float* Wptr = W + (size_t)(n0 + lrow) * Dd + lcol;

    float4 a0 = *(const float4*)(Aptr);
    float4 a1 = *(const float4*)(Aptr + (size_t)64 * Dd);
    float4 b0 = *(const float4*)(Wptr);
    float4 b1 = *(const float4*)(Wptr + (size_t)64 * Dd);

    unsigned long long acc2[8][4];
#pragma unroll
    for (int i = 0; i < 8; i++)
#pragma unroll
        for (int j = 0; j < 4; j++) acc2[i][j] = 0ULL;

    for (int k0 = 0; k0 < Dd; k0 += 16) {
        __syncthreads();
        As[lcol + 0][lrow] = a0.x; As[lcol + 1][lrow] = a0.y;
        As[lcol + 2][lrow] = a0.z; As[lcol + 3][lrow] = a0.w;
        As[lcol + 0][lrow + 64] = a1.x; As[lcol + 1][lrow + 64] = a1.y;
        As[lcol + 2][lrow + 64] = a1.z; As[lcol + 3][lrow + 64] = a1.w;
        Bs[lcol + 0][lrow] = b0.x; Bs[lcol + 1][lrow] = b0.y;
        Bs[lcol + 2][lrow] = b0.z; Bs[lcol + 3][lrow] = b0.w;
        Bs[lcol + 0][lrow + 64] = b1.x; Bs[lcol + 1][lrow + 64] = b1.y;
        Bs[lcol + 2][lrow + 64] = b1.z; Bs[lcol + 3][lrow + 64] = b1.w;
        __syncthreads();

        if (k0 + 16 < Dd) {
            a0 = *(const float4*)(Aptr + k0 + 16);
            a1 = *(const float4*)(Aptr + (size_t)64 * Dd + k0 + 16);
            b0 = *(const float4*)(Wptr + k0 + 16);
            b1 = *(const float4*)(Wptr + (size_t)64 * Dd + k0 + 16);
        }

#pragma unroll
        for (int k = 0; k < 16; k++) {
            float ar[8];
            *(float4*)(ar) = *(const float4*)&As[k][ty * 8];
            *(float4*)(ar + 4) = *(const float4*)&As[k][ty * 8 + 4];
            unsigned long long brp[4];
            const unsigned long long* b64 = (const unsigned long long*)&Bs[k][tx * 8];
            brp[0] = b64[0]; brp[1] = b64[1]; brp[2] = b64[2]; brp[3] = b64[3];
#pragma unroll
            for (int i = 0; i < 8; i++) {
                unsigned long long ad = pk2(ar[i], ar[i]);
#pragma unroll
                for (int j = 0; j < 4; j++) fma2(acc2[i][j], ad, brp[j]);
            }
        }
    }

    float bj[8];
#pragma unroll
    for (int j = 0; j < 8; j++) bj[j] = bias[n0 + tx * 8 + j];
#pragma unroll
    for (int i = 0; i < 8; i++) {
        float* Crow = g_pre + (size_t)(m0 + ty * 8 + i) * Dd + n0 + tx * 8;
        float c[8];
#pragma unroll
        for (int j = 0; j < 4; j++) {
            float2 f = up2(acc2[i][j]);
            c[2 * j] = f.x + bj[2 * j];
            c[2 * j + 1] = f.y + bj[2 * j + 1];
        }
        *(float4*)(Crow) = make_float4(c[0], c[1], c[2], c[3]);
        *(float4*)(Crow + 4) = make_float4(c[4], c[5], c[6], c[7]);
    }
}

// fast tanh via __expf (rel err ~1e-6 end-to-end; threshold is 1e-3)
__device__ __forceinline__ float ftanh(float x) {
    float e = __expf(2.f * x);
    return 1.f - 2.f / (e + 1.f);
}

// ---------------- persistent recurrence -------------------------------------
// 128 CTAs = 4 independent batch groups x 32 CTAs. CTA = 32 dims x 4 batches,
// W slice 128KB persistent in SMEM. Atomic-free barrier: producer j does one
// st.release.gpu to its own flag word (group's 32 flags in ONE 128B line);
// warp 0 polls with a single coalesced 32-lane acquire load + ballot.
// Compute: warp = 4 dims x 4 batches; lane (b=lane>>3, g=lane&7) owns one
// 16B h-granule per 8-granule chunk; h via default-cached LDG (L1 dedups the
// 8 warps); W via LDS.128 with 4x broadcast; 7-shfl.64 fold; lanes g<4 do the
// epilogue (one output each).
__global__ void __launch_bounds__(256, 1) recurrent_kernel(
        const float* __restrict__ z, const float* __restrict__ h0,
        float* __restrict__ outs, float* __restrict__ hall) {
    extern __shared__ float smem[];
    float* sW = smem;                                  // [DC][Dd] = 128 KB

    const int tid = threadIdx.x, bid = blockIdx.x;
    const int grp = bid >> 5;               // batch / sync group
    const int cidx = bid & 31;              // producer index within group
    const int dbase = cidx * DC;
    const int bbase = grp * 4;
    unsigned* flags = &g_flags[grp * CPG];
    unsigned* myflag = flags + cidx;

    // preload my W_h_eff rows (persist across all steps)
    {
        const float4* wsrc = (const float4*)(g_WhEff + (size_t)dbase * Dd);
        for (int i = tid; i < DC * Dd / 4; i += 256) ((float4*)sW)[i] = wsrc[i];
    }
    // h_all[0] stripe (pure output; consumers read the h0 input directly)
    if (tid < 128) {
        int b = bbase + (tid >> 5), d = dbase + (tid & 31);
        hall[b * Dd + d] = h0[b * Dd + d];
    }
    __syncthreads();

    const int w = tid >> 5, lane = tid & 31;
    const int b = lane >> 3, g = lane & 7;
    const int myb = bbase + b;
    const bool epi = (g < 4);
    const int ed = dbase + w * 4 + g;          // valid when epi
    const ulonglong2* w128 = (const ulonglong2*)sW;

    for (int t = 0; t < Tt; t++) {
        const size_t off_e = (size_t)t * Bb * Dd + (size_t)myb * Dd + ed;
        float pre_v = 0.f, z_v = 0.f;
        if (epi) {                      // DRAM prefetch; overlaps the wait
            pre_v = __ldcg(g_pre + off_e);
            z_v = __ldcg(z + off_e);
        }

        // wait for all 32 producer slices of h[t] (skip at t=0)
        if (t > 0) {
            if (w == 0) {
                unsigned f;
                do {
                    asm volatile("ld.acquire.gpu.global.u32 %0, [%1];"
                                 : "=r"(f) : "l"(flags + lane) : "memory");
                } while (__ballot_sync(0xffffffffu, f < (unsigned)t) != 0u);
            }
            __syncthreads();
        }

        // h[t] for my batch, streamed via L1-cached LDG (8 warps dedup in L1)
        const float* hb = ((t == 0) ? h0 : (hall + (size_t)t * Bb * Dd))
                          + (size_t)myb * Dd;

        unsigned long long acc[4] = {0ULL, 0ULL, 0ULL, 0ULL};
#pragma unroll 8
        for (int j = 0; j < 32; j++) {
            const ulonglong2 hv = *(const ulonglong2*)(hb + j * 32 + g * 4);
#pragma unroll
            for (int d = 0; d < 4; d++) {
                const ulonglong2 wv = w128[(w * 4 + d) * 256 + j * 8 + g];
                fma2(acc[d], wv.x, hv.x);
                fma2(acc[d], wv.y, hv.y);
            }
        }

        // reduce over the 8-lane g-group (batch fixed): xor-4, fold-2, fold-1
#pragma unroll
        for (int d = 0; d < 4; d++)
            acc[d] = add2(acc[d], __shfl_xor_sync(0xffffffffu, acc[d], 4));
#pragma unroll
        for (int j = 0; j < 2; j++) {
            unsigned long long send = (g & 2) ? acc[j] : acc[j + 2];
            unsigned long long recv = __shfl_xor_sync(0xffffffffu, send, 2);
            acc[j] = add2((g & 2) ? acc[j + 2] : acc[j], recv);
        }
        {
            unsigned long long send = (g & 1) ? acc[0] : acc[1];
            unsigned long long recv = __shfl_xor_sync(0xffffffffu, send, 1);
            acc[0] = add2((g & 1) ? acc[1] : acc[0], recv);
        }
        const float2 f2 = up2(acc[0]);
        const float val = f2.x + f2.y;

        // epilogue part 1: h store only (the signal-critical data)
        float hn = 0.f;
        if (epi) {
            hn = ftanh(val + pre_v);
            hall[off_e + Bb * Dd] = hn;            // h_all[t+1]
        }
        __syncthreads();                 // all h stores of this slice issued
        if (tid == 0) {
            asm volatile("st.release.gpu.global.u32 [%0], %1;"
                         :: "l"(myflag), "r"((unsigned)(t + 1)) : "memory");
        }
        // epilogue part 2: silu-gated output, off the signal path
        if (epi) {
            float sg = z_v / (1.f + __expf(-z_v));
            outs[off_e] = hn * sg;
        }
    }
}

// ---------------- launch ----------------
extern "C" void kernel_launch(void* const* d_in, const int* in_sizes, int n_in,
                              void* d_out, int out_size) {
    const float* x   = (const float*)d_in[0];  // [T,B,D]
    const float* z   = (const float*)d_in[1];  // [T,B,D]
    const float* h0  = (const float*)d_in[2];  // [B,D]
    const float* Wx  = (const float*)d_in[3];  // [D,D]
    const float* Wh  = (const float*)d_in[4];  // [D,D]
    const float* lr  = (const float*)d_in[5];  // [D]
    const float* bia = (const float*)d_in[6];  // [D]
    const float* u0  = (const float*)d_in[7];  // [D]

    float* outs = (float*)d_out;                         // [T,B,D]
    float* hall = (float*)d_out + (size_t)Tt * Bb * Dd;  // [T+1,B,D]

    const size_t rec_smem = (size_t)DC * Dd * sizeof(float);  // 128 KB
    cudaFuncSetAttribute(recurrent_kernel,
                         cudaFuncAttributeMaxDynamicSharedMemorySize,
                         (int)rec_smem);

    init_kernel<<<1, 128>>>();
    power_iter_kernel<<<1, 1024>>>(Wh, u0);
    scale_wh_kernel<<<Dd, 256>>>(Wh, lr);
    {
        dim3 grid(Dd / 128, (Tt * Bb) / 128);  // (8, 128)
        gemm_kernel<<<grid, 256>>>(x, Wx, bia);
    }
    recurrent_kernel<<<NBLK, 256, rec_smem>>>(z, h0, outs, hall);
}